// round 15
// baseline (speedup 1.0000x reference)
#include <cuda_runtime.h>
#include <cuda_fp16.h>
#include <math.h>
#include <stdint.h>

// Problem constants
#define B_   4
#define S_   2048
#define H_   2048
#define NH_  16
#define NKV_ 4
#define HD_  128
#define F_   3072          // H + 2*NKV*HD
#define KC_  64            // GEMM K-chunk

// ---------------------------------------------------------------------------
// Scratch (device globals: allocation-free per harness rules)
// ---------------------------------------------------------------------------
__device__ __half g_x[(size_t)B_ * S_ * H_];           // GEMM A (hidden, then attn O)
__device__ __half g_wa[(size_t)H_ * F_];               // w_attn fp16 [2048,3072] (orig layout)
__device__ __half g_wp[(size_t)H_ * H_];               // w_proj fp16 [2048,2048] (orig layout)

__device__ __half g_q[(size_t)B_ * NH_ * S_ * HD_];    // Q fp16 (pre-scaled)
__device__ __half g_k[(size_t)B_ * NKV_ * S_ * HD_];   // K fp16
__device__ __half g_v[(size_t)B_ * NKV_ * S_ * HD_];   // V fp16

// ---------------------------------------------------------------------------
// Arch-neutral PTX helpers (tcgen05 unavailable under compute_103 target)
// ---------------------------------------------------------------------------
__device__ __forceinline__ uint32_t smem_u32(const void* p) {
    uint32_t a;
    asm("{ .reg .u64 t; cvta.to.shared.u64 t, %1; cvt.u32.u64 %0, t; }" : "=r"(a) : "l"(p));
    return a;
}
__device__ __forceinline__ void cp16(uint32_t saddr, const void* g) {
    asm volatile("cp.async.cg.shared.global [%0], [%1], 16;" :: "r"(saddr), "l"(g));
}
#define CP_COMMIT() asm volatile("cp.async.commit_group;" ::: "memory")
#define CP_WAIT(n)  asm volatile("cp.async.wait_group %0;" :: "n"(n) : "memory")

__device__ __forceinline__ void ldsm_x4(uint32_t* r, uint32_t addr) {
    asm volatile("ldmatrix.sync.aligned.m8n8.x4.shared.b16 {%0,%1,%2,%3}, [%4];"
                 : "=r"(r[0]), "=r"(r[1]), "=r"(r[2]), "=r"(r[3]) : "r"(addr));
}
__device__ __forceinline__ void ldsm_x4_t(uint32_t* r, uint32_t addr) {
    asm volatile("ldmatrix.sync.aligned.m8n8.x4.trans.shared.b16 {%0,%1,%2,%3}, [%4];"
                 : "=r"(r[0]), "=r"(r[1]), "=r"(r[2]), "=r"(r[3]) : "r"(addr));
}
__device__ __forceinline__ void mma_f16(float* c, const uint32_t* a, const uint32_t* b) {
    asm volatile(
        "mma.sync.aligned.m16n8k16.row.col.f32.f16.f16.f32 "
        "{%0,%1,%2,%3}, {%4,%5,%6,%7}, {%8,%9}, {%0,%1,%2,%3};"
        : "+f"(c[0]), "+f"(c[1]), "+f"(c[2]), "+f"(c[3])
        : "r"(a[0]), "r"(a[1]), "r"(a[2]), "r"(a[3]), "r"(b[0]), "r"(b[1]));
}
__device__ __forceinline__ uint32_t swz(uint32_t off) {  // SW128
    return off ^ ((off >> 3) & 0x70);
}
__device__ __forceinline__ uint32_t pkh(__half a, __half b) {
    uint16_t x = *(uint16_t*)&a, y = *(uint16_t*)&b;
    return ((uint32_t)y << 16) | x;
}

// ---------------------------------------------------------------------------
// prep: plain coalesced fp32 -> fp16 conversion (no transpose needed anymore)
// ---------------------------------------------------------------------------
__global__ __launch_bounds__(256) void conv2h(
    const float* __restrict__ x, __half* __restrict__ o, int n4)
{
    int i = blockIdx.x * 256 + threadIdx.x;
    if (i >= n4) return;
    float4 v = *((const float4*)x + i);
    ((uint32_t*)o)[i * 2]     = pkh(__float2half(v.x), __float2half(v.y));
    ((uint32_t*)o)[i * 2 + 1] = pkh(__float2half(v.z), __float2half(v.w));
}

// ---------------------------------------------------------------------------
// GEMM building blocks. A: [M,K] fp16 row-major (K-major, ldsm non-trans).
// B: [K,N] fp16 row-major (ORIGINAL weight layout) — loaded flash-PV style:
//   tile = 64 k-rows x 128 n-cols = two 8KB SW128 blocks (n-block = n>=64),
//   fragments via ldmatrix.trans (same pattern as flash PV, validated R4-R14).
// CTA 128x128, 8 warps, warp tile 64x32, 2-stage cp.async, 2 CTAs/SM.
// ---------------------------------------------------------------------------
#define GSTG1 32768

// shared mainloop macro-ish helpers via inline functions are awkward; keep two
// kernels with identical bodies except the epilogue.

__global__ __launch_bounds__(256, 2) void gemm_fp16(
    const __half* __restrict__ A, const __half* __restrict__ B,
    float* __restrict__ C, int M, int N, int K)
{
    extern __shared__ __align__(128) char smem[];
    const uint32_t sbase = smem_u32(smem);
    const int tid = threadIdx.x;
    const int wid = tid >> 5, lane = tid & 31;
    const int bm = blockIdx.y * 128, bn = blockIdx.x * 128;

    const __half* gA = A + (size_t)bm * K;
    const __half* gB = B + bn;

    const int nchunks = K / KC_;

    auto load_stage = [&](int c, int buf) {
        const int k0 = c * KC_;
        const uint32_t db = sbase + (uint32_t)buf * GSTG1;
        // A tile: [128 rows][64 k] fp16, K-major, 1024 chunks
        #pragma unroll
        for (int it = 0; it < 4; it++) {
            int i = tid + it * 256;
            int row = i >> 3, c8 = i & 7;
            cp16(db + swz((uint32_t)(row * 128 + c8 * 16)),
                 gA + (size_t)row * K + k0 + c8 * 8);
        }
        // B tile: [64 k-rows][128 n] fp16 from [K,N]; two 8KB blocks
        #pragma unroll
        for (int it = 0; it < 4; it++) {
            int i = tid + it * 256;
            int row = i >> 4, c16 = i & 15;
            cp16(db + 16384 + (uint32_t)(c16 >> 3) * 8192 +
                     swz((uint32_t)(row * 128 + (c16 & 7) * 16)),
                 gB + (size_t)(k0 + row) * N + c16 * 8);
        }
    };

    load_stage(0, 0); CP_COMMIT();
    if (nchunks > 1) load_stage(1, 1);
    CP_COMMIT();

    const int wm = wid >> 2, wn = wid & 3;
    const int m0 = wm * 64, n0 = wn * 32;

    float acc[4][4][4];
    #pragma unroll
    for (int i = 0; i < 4; i++)
        #pragma unroll
        for (int j = 0; j < 4; j++)
            #pragma unroll
            for (int k = 0; k < 4; k++) acc[i][j][k] = 0.f;

    const int aRow = (lane & 15);
    const int aKb  = (lane >> 4) * 16;
    const int bKrow = lane & 15;              // k-row within 16
    const int bNb   = (lane >> 4) * 16;       // +16B for lanes 16-31

    for (int c = 0; c < nchunks; c++) {
        CP_WAIT(1);
        __syncthreads();
        const int buf = c & 1;
        const uint32_t sA = sbase + (uint32_t)buf * GSTG1;
        const uint32_t sB = sA + 16384;

        #pragma unroll
        for (int ks = 0; ks < 4; ks++) {
            const uint32_t akb = (uint32_t)(ks * 32 + aKb);
            uint32_t af[4][4], bf[2][4];
            #pragma unroll
            for (int mt = 0; mt < 4; mt++) {
                uint32_t off = swz((uint32_t)((m0 + mt * 16 + aRow) * 128) + akb);
                ldsm_x4(af[mt], sA + off);
            }
            #pragma unroll
            for (int g = 0; g < 2; g++) {     // two n16 groups of the n32 warp tile
                int nb = n0 + g * 16;
                uint32_t off = (uint32_t)(nb >> 6) * 8192 +
                               swz((uint32_t)((ks * 16 + bKrow) * 128 +
                                              (nb & 63) * 2 + bNb));
                ldsm_x4_t(bf[g], sB + off);
            }
            #pragma unroll
            for (int mt = 0; mt < 4; mt++)
                #pragma unroll
                for (int g = 0; g < 2; g++)
                    #pragma unroll
                    for (int p = 0; p < 2; p++)
                        mma_f16(acc[mt][g * 2 + p], af[mt], &bf[g][p * 2]);
        }
        __syncthreads();
        if (c + 2 < nchunks) load_stage(c + 2, buf);
        CP_COMMIT();
    }

    const int er = lane >> 2, ec = (lane & 3) * 2;
    #pragma unroll
    for (int mt = 0; mt < 4; mt++)
        #pragma unroll
        for (int nt = 0; nt < 4; nt++) {
            int row = bm + m0 + mt * 16 + er;
            int col = bn + n0 + nt * 8 + ec;
            *(float2*)(C + (size_t)row * N + col) =
                make_float2(acc[mt][nt][0], acc[mt][nt][1]);
            *(float2*)(C + (size_t)(row + 8) * N + col) =
                make_float2(acc[mt][nt][2], acc[mt][nt][3]);
        }
}

// ---------------------------------------------------------------------------
// QKV GEMM (same B-from-[K,N] mainloop) with fused RoPE epilogue.
// Each 128-col tile of F is one head (group of 768 = 4 q | k | v).
// ---------------------------------------------------------------------------
__global__ __launch_bounds__(256, 2) void gemm_qkv(
    const __half* __restrict__ A, const __half* __restrict__ B,
    const float* __restrict__ rope_cos, const float* __restrict__ rope_sin,
    __half* __restrict__ q_out, __half* __restrict__ k_out,
    __half* __restrict__ v_out, int M, int N, int K)
{
    extern __shared__ __align__(128) char smem[];
    const uint32_t sbase = smem_u32(smem);
    const int tid = threadIdx.x;
    const int wid = tid >> 5, lane = tid & 31;
    const int bm = blockIdx.y * 128, bn = blockIdx.x * 128;

    const __half* gA = A + (size_t)bm * K;
    const __half* gB = B + bn;

    const int nchunks = K / KC_;

    auto load_stage = [&](int c, int buf) {
        const int k0 = c * KC_;
        const uint32_t db = sbase + (uint32_t)buf * GSTG1;
        #pragma unroll
        for (int it = 0; it < 4; it++) {
            int i = tid + it * 256;
            int row = i >> 3, c8 = i & 7;
            cp16(db + swz((uint32_t)(row * 128 + c8 * 16)),
                 gA + (size_t)row * K + k0 + c8 * 8);
        }
        #pragma unroll
        for (int it = 0; it < 4; it++) {
            int i = tid + it * 256;
            int row = i >> 4, c16 = i & 15;
            cp16(db + 16384 + (uint32_t)(c16 >> 3) * 8192 +
                     swz((uint32_t)(row * 128 + (c16 & 7) * 16)),
                 gB + (size_t)(k0 + row) * N + c16 * 8);
        }
    };

    load_stage(0, 0); CP_COMMIT();
    if (nchunks > 1) load_stage(1, 1);
    CP_COMMIT();

    const int wm = wid >> 2, wn = wid & 3;
    const int m0 = wm * 64, n0 = wn * 32;

    float acc[4][4][4];
    #pragma unroll
    for (int i = 0; i < 4; i++)
        #pragma unroll
        for (int j = 0; j < 4; j++)
            #pragma unroll
            for (int k = 0; k < 4; k++) acc[i][j][k] = 0.f;

    const int aRow = (lane & 15);
    const int aKb  = (lane >> 4) * 16;
    const int bKrow = lane & 15;
    const int bNb   = (lane >> 4) * 16;

    for (int c = 0; c < nchunks; c++) {
        CP_WAIT(1);
        __syncthreads();
        const int buf = c & 1;
        const uint32_t sA = sbase + (uint32_t)buf * GSTG1;
        const uint32_t sB = sA + 16384;

        #pragma unroll
        for (int ks = 0; ks < 4; ks++) {
            const uint32_t akb = (uint32_t)(ks * 32 + aKb);
            uint32_t af[4][4], bf[2][4];
            #pragma unroll
            for (int mt = 0; mt < 4; mt++) {
                uint32_t off = swz((uint32_t)((m0 + mt * 16 + aRow) * 128) + akb);
                ldsm_x4(af[mt], sA + off);
            }
            #pragma unroll
            for (int g = 0; g < 2; g++) {
                int nb = n0 + g * 16;
                uint32_t off = (uint32_t)(nb >> 6) * 8192 +
                               swz((uint32_t)((ks * 16 + bKrow) * 128 +
                                              (nb & 63) * 2 + bNb));
                ldsm_x4_t(bf[g], sB + off);
            }
            #pragma unroll
            for (int mt = 0; mt < 4; mt++)
                #pragma unroll
                for (int g = 0; g < 2; g++)
                    #pragma unroll
                    for (int p = 0; p < 2; p++)
                        mma_f16(acc[mt][g * 2 + p], af[mt], &bf[g][p * 2]);
        }
        __syncthreads();
        if (c + 2 < nchunks) load_stage(c + 2, buf);
        CP_COMMIT();
    }

    // ---- fused RoPE epilogue (stage fp32 tile in smem) ----
    __syncthreads();
    float* smf = (float*)smem;               // fp32 tile [128][132]
    const int er = lane >> 2, ec = (lane & 3) * 2;
    #pragma unroll
    for (int mt = 0; mt < 4; mt++)
        #pragma unroll
        for (int nt = 0; nt < 4; nt++) {
            int r = m0 + mt * 16 + er;
            int cc = n0 + nt * 8 + ec;
            smf[r * 132 + cc]           = acc[mt][nt][0];
            smf[r * 132 + cc + 1]       = acc[mt][nt][1];
            smf[(r + 8) * 132 + cc]     = acc[mt][nt][2];
            smf[(r + 8) * 132 + cc + 1] = acc[mt][nt][3];
        }
    __syncthreads();

    const int chunk = (int)blockIdx.x % 6;   // 0-3: q heads, 4: k, 5: v
    const int grp   = (int)blockIdx.x / 6;   // kv group
    const float qscale = 0.08838834764831845f * 1.4426950408889634f;

    #pragma unroll 4
    for (int it = 0; it < 32; it++) {
        int p = tid + it * 256;
        int r = p >> 6, dd = (p & 63) * 2;
        int tok = bm + r, b = tok >> 11, s = tok & 2047;
        float v0 = smf[r * 132 + dd], v1 = smf[r * 132 + dd + 1];
        if (chunk < 5) {
            float o0, o1;
            if (dd < 64) { o0 = -smf[r * 132 + dd + 64]; o1 = -smf[r * 132 + dd + 65]; }
            else         { o0 =  smf[r * 132 + dd - 64]; o1 =  smf[r * 132 + dd - 63]; }
            float2 cs = *(const float2*)(rope_cos + (size_t)s * HD_ + dd);
            float2 sn = *(const float2*)(rope_sin + (size_t)s * HD_ + dd);
            v0 = v0 * cs.x + o0 * sn.x;
            v1 = v1 * cs.y + o1 * sn.y;
            if (chunk < 4) { v0 *= qscale; v1 *= qscale; }
        }
        uint32_t pv = pkh(__float2half(v0), __float2half(v1));
        if (chunk < 4) {
            int hh = grp * 4 + chunk;
            *(uint32_t*)(q_out + (((size_t)b * NH_ + hh) * S_ + s) * HD_ + dd) = pv;
        } else if (chunk == 4) {
            *(uint32_t*)(k_out + (((size_t)b * NKV_ + grp) * S_ + s) * HD_ + dd) = pv;
        } else {
            *(uint32_t*)(v_out + (((size_t)b * NKV_ + grp) * S_ + s) * HD_ + dd) = pv;
        }
    }
}

// ---------------------------------------------------------------------------
// Tensor-core causal flash attention, single fp16, GQA (EXACT R12/R14 version
// — best measured). S = Q K^T (1 MMA); O += P V (1 MMA). 1 CTA/SM.
// smem: Q 32KB; per stage K,V 16KB each (2 stages) = 96KB.
// ---------------------------------------------------------------------------
__global__ __launch_bounds__(256, 1) void flash_mma(
    const __half* __restrict__ Q, const __half* __restrict__ Kh,
    const __half* __restrict__ Vh, __half* __restrict__ O_out)
{
    extern __shared__ __align__(128) char smem[];
    const uint32_t sb = smem_u32(smem);
    const int tid = threadIdx.x, lane = tid & 31, w = tid >> 5;
    const int qt = (int)(gridDim.x - 1) - (int)blockIdx.x;   // heavy tiles first
    const int h = blockIdx.y, b = blockIdx.z;
    const int kvh = h >> 2;

    const __half* gQ = Q + (((size_t)b * NH_ + h) * S_ + (size_t)qt * 128) * HD_;
    const size_t kvbase = ((size_t)b * NKV_ + kvh) * S_ * HD_;
    const __half* gKh = Kh + kvbase;
    const __half* gVh = Vh + kvbase;

    #pragma unroll
    for (int it = 0; it < 8; it++) {
        int i = tid + it * 256;
        int row = i >> 4, c8 = i & 15;
        uint32_t so = (uint32_t)(c8 >> 3) * 16384 +
                      swz((uint32_t)(row * 128 + (c8 & 7) * 16));
        cp16(sb + so, gQ + (size_t)row * HD_ + c8 * 8);
    }
    CP_COMMIT();

    auto load_stage = [&](int kt, int buf) {
        uint32_t o = 32768 + (uint32_t)buf * 32768;
        const size_t go = (size_t)kt * 64 * HD_;
        #pragma unroll
        for (int it = 0; it < 4; it++) {
            int i = tid + it * 256;
            int row = i >> 4, c8 = i & 15;
            uint32_t so = (uint32_t)(c8 >> 3) * 8192 +
                          swz((uint32_t)(row * 128 + (c8 & 7) * 16));
            size_t gof = go + (size_t)row * HD_ + c8 * 8;
            cp16(sb + o + so,         gKh + gof);
            cp16(sb + o + 16384 + so, gVh + gof);
        }
    };

    load_stage(0, 0);
    CP_COMMIT();

    const int nkt = 2 * qt + 2;

    float O[16][4];
    #pragma unroll
    for (int i = 0; i < 16; i++)
        #pragma unroll
        for (int j = 0; j < 4; j++) O[i][j] = 0.f;
    float mA = -1e30f, mB = -1e30f, lA = 0.f, lB = 0.f;

    const int aRow = lane & 15;
    const int aK16 = (lane >> 4) * 16;
    const int bRow = (lane & 7) + ((lane >> 4) & 1) * 8;
    const int bK16 = ((lane >> 3) & 1) * 16;

    for (int kt = 0; kt < nkt; kt++) {
        const int buf = kt & 1;
        if (kt + 1 < nkt) { load_stage(kt + 1, buf ^ 1); CP_COMMIT(); CP_WAIT(1); }
        else              { CP_WAIT(0); }
        __syncthreads();

        const uint32_t sK = sb + 32768 + (uint32_t)buf * 32768;
        const uint32_t sV = sK + 16384;

        float S[8][4];
        #pragma unroll
        for (int i = 0; i < 8; i++)
            #pragma unroll
            for (int j = 0; j < 4; j++) S[i][j] = 0.f;

        #pragma unroll
        for (int ks = 0; ks < 8; ks++) {
            uint32_t qo = (uint32_t)(ks >> 2) * 16384 +
                          swz((uint32_t)((w * 16 + aRow) * 128 + (ks & 3) * 32 + aK16));
            uint32_t qf[4];
            ldsm_x4(qf, sb + qo);
            #pragma unroll
            for (int g = 0; g < 4; g++) {
                uint32_t ko = (uint32_t)(ks >> 2) * 8192 +
                              swz((uint32_t)((g * 16 + bRow) * 128 + (ks & 3) * 32 + bK16));
                uint32_t khf[4];
                ldsm_x4(khf, sK + ko);
                #pragma unroll
                for (int p = 0; p < 2; p++)
                    mma_f16(S[g * 2 + p], qf, &khf[p * 2]);
            }
        }

        if (kt >= 2 * qt) {
            const int rA = qt * 128 + w * 16 + (lane >> 2);
            #pragma unroll
            for (int nt = 0; nt < 8; nt++) {
                int key0 = kt * 64 + nt * 8 + (lane & 3) * 2;
                if (key0     > rA)     S[nt][0] = -1e30f;
                if (key0 + 1 > rA)     S[nt][1] = -1e30f;
                if (key0     > rA + 8) S[nt][2] = -1e30f;
                if (key0 + 1 > rA + 8) S[nt][3] = -1e30f;
            }
        }

        float mxA = -1e30f, mxB = -1e30f;
        #pragma unroll
        for (int nt = 0; nt < 8; nt++) {
            mxA = fmaxf(mxA, fmaxf(S[nt][0], S[nt][1]));
            mxB = fmaxf(mxB, fmaxf(S[nt][2], S[nt][3]));
        }
        #pragma unroll
        for (int off = 1; off < 4; off <<= 1) {
            mxA = fmaxf(mxA, __shfl_xor_sync(0xffffffffu, mxA, off));
            mxB = fmaxf(mxB, __shfl_xor_sync(0xffffffffu, mxB, off));
        }
        float mAn = fmaxf(mA, mxA), mBn = fmaxf(mB, mxB);
        float aAl = exp2f(mA - mAn), aBl = exp2f(mB - mBn);
        mA = mAn; mB = mBn;

        float sumA = 0.f, sumB = 0.f;
        #pragma unroll
        for (int nt = 0; nt < 8; nt++) {
            S[nt][0] = exp2f(S[nt][0] - mA);
            S[nt][1] = exp2f(S[nt][1] - mA);
            S[nt][2] = exp2f(S[nt][2] - mB);
            S[nt][3] = exp2f(S[nt][3] - mB);
            sumA += S[nt][0] + S[nt][1];
            sumB += S[nt][2] + S[nt][3];
        }
        #pragma unroll
        for (int off = 1; off < 4; off <<= 1) {
            sumA += __shfl_xor_sync(0xffffffffu, sumA, off);
            sumB += __shfl_xor_sync(0xffffffffu, sumB, off);
        }
        lA = lA * aAl + sumA;
        lB = lB * aBl + sumB;
        #pragma unroll
        for (int nt = 0; nt < 16; nt++) {
            O[nt][0] *= aAl; O[nt][1] *= aAl;
            O[nt][2] *= aBl; O[nt][3] *= aBl;
        }

        #pragma unroll
        for (int kk = 0; kk < 4; kk++) {
            uint32_t ah[4];
            ah[0] = pkh(__float2half(S[2 * kk][0]),     __float2half(S[2 * kk][1]));
            ah[1] = pkh(__float2half(S[2 * kk][2]),     __float2half(S[2 * kk][3]));
            ah[2] = pkh(__float2half(S[2 * kk + 1][0]), __float2half(S[2 * kk + 1][1]));
            ah[3] = pkh(__float2half(S[2 * kk + 1][2]), __float2half(S[2 * kk + 1][3]));
            #pragma unroll
            for (int g = 0; g < 8; g++) {
                uint32_t vo = (uint32_t)(g >> 2) * 8192 +
                              swz((uint32_t)((kk * 16 + (lane & 15)) * 128 +
                                             (g & 3) * 32 + (lane >> 4) * 16));
                uint32_t vhf[4];
                ldsm_x4_t(vhf, sV + vo);
                #pragma unroll
                for (int p = 0; p < 2; p++)
                    mma_f16(O[g * 2 + p], ah, &vhf[p * 2]);
            }
        }
        __syncthreads();
    }

    const float iA = 1.f / lA, iB = 1.f / lB;
    const int sA = qt * 128 + w * 16 + (lane >> 2);
    const size_t baseA = ((size_t)b * S_ + sA) * H_ + (size_t)h * HD_;
    const size_t baseB = baseA + (size_t)8 * H_;
    #pragma unroll
    for (int nt = 0; nt < 16; nt++) {
        int col = nt * 8 + (lane & 3) * 2;
        *(uint32_t*)(O_out + baseA + col) =
            pkh(__float2half(O[nt][0] * iA), __float2half(O[nt][1] * iA));
        *(uint32_t*)(O_out + baseB + col) =
            pkh(__float2half(O[nt][2] * iB), __float2half(O[nt][3] * iB));
    }
}

// ---------------------------------------------------------------------------
// Launch
// ---------------------------------------------------------------------------
extern "C" void kernel_launch(void* const* d_in, const int* in_sizes, int n_in,
                              void* d_out, int out_size)
{
    (void)in_sizes; (void)n_in; (void)out_size;
    const float* hidden   = (const float*)d_in[0];
    // d_in[1] = attention_mask: structurally causal, unused (exp(-1e9) == 0 in fp32)
    const float* rope_cos = (const float*)d_in[2];
    const float* rope_sin = (const float*)d_in[3];
    const float* w_attn   = (const float*)d_in[4];
    const float* w_proj   = (const float*)d_in[5];
    float* out = (float*)d_out;

    __half *p_x, *p_wa, *p_wp, *p_q, *p_k, *p_v;
    cudaGetSymbolAddress((void**)&p_x, g_x);
    cudaGetSymbolAddress((void**)&p_wa, g_wa);
    cudaGetSymbolAddress((void**)&p_wp, g_wp);
    cudaGetSymbolAddress((void**)&p_q, g_q);
    cudaGetSymbolAddress((void**)&p_k, g_k);
    cudaGetSymbolAddress((void**)&p_v, g_v);

    const int gemm_smem = 2 * GSTG1;            // 64 KB
    cudaFuncSetAttribute(gemm_fp16, cudaFuncAttributeMaxDynamicSharedMemorySize, gemm_smem);
    const int qkv_smem = 128 * 132 * 4;         // 67.6 KB (>= pipeline 64KB)
    cudaFuncSetAttribute(gemm_qkv, cudaFuncAttributeMaxDynamicSharedMemorySize, qkv_smem);
    const int flash_smem = 32768 + 2 * 32768;   // 96 KB
    cudaFuncSetAttribute(flash_mma, cudaFuncAttributeMaxDynamicSharedMemorySize, flash_smem);

    const int MTOK = B_ * S_;

    // 0) prep: plain fp32->fp16 conversion (weights keep original [K,N] layout)
    conv2h<<<(H_ * F_ / 4 + 255) / 256, 256>>>(w_attn, p_wa, H_ * F_ / 4);
    conv2h<<<(H_ * H_ / 4 + 255) / 256, 256>>>(w_proj, p_wp, H_ * H_ / 4);
    conv2h<<<(MTOK * H_ / 4 + 255) / 256, 256>>>(hidden, p_x, MTOK * H_ / 4);

    // 1) QKV projection + fused RoPE -> q/k/v fp16 heads directly
    gemm_qkv<<<dim3(F_ / 128, MTOK / 128), 256, qkv_smem>>>(
        p_x, p_wa, rope_cos, rope_sin, p_q, p_k, p_v, MTOK, F_, H_);

    // 2) Tensor-core causal flash attention (fp16) -> x (fp16)
    flash_mma<<<dim3(S_ / 128, NH_, B_), 256, flash_smem>>>(p_q, p_k, p_v, p_x);

    // 3) output projection (fp16 in, fp32 out): [8192,2048] @ [2048,2048]
    gemm_fp16<<<dim3(H_ / 128, MTOK / 128), 256, gemm_smem>>>(
        p_x, p_wp, out, MTOK, H_, H_);
}

// round 16
// speedup vs baseline: 1.0692x; 1.0692x over previous
#include <cuda_runtime.h>
#include <cuda_fp16.h>
#include <math.h>
#include <stdint.h>

// Problem constants
#define B_   4
#define S_   2048
#define H_   2048
#define NH_  16
#define NKV_ 4
#define HD_  128
#define F_   3072          // H + 2*NKV*HD
#define KC_  64            // GEMM K-chunk

// ---------------------------------------------------------------------------
// Scratch (device globals: allocation-free per harness rules)
// ---------------------------------------------------------------------------
__device__ __half g_x[(size_t)B_ * S_ * H_];           // GEMM A (hidden, then attn O)
__device__ __half g_wa[(size_t)F_ * H_];               // w_attn^T fp16 [3072,2048]
__device__ __half g_wp[(size_t)H_ * H_];               // w_proj^T fp16 [2048,2048]

__device__ __half g_q[(size_t)B_ * NH_ * S_ * HD_];    // Q fp16 (pre-scaled)
__device__ __half g_k[(size_t)B_ * NKV_ * S_ * HD_];   // K fp16
__device__ __half g_v[(size_t)B_ * NKV_ * S_ * HD_];   // V fp16

// ---------------------------------------------------------------------------
// Arch-neutral PTX helpers (tcgen05 unavailable under compute_103 target)
// ---------------------------------------------------------------------------
__device__ __forceinline__ uint32_t smem_u32(const void* p) {
    uint32_t a;
    asm("{ .reg .u64 t; cvta.to.shared.u64 t, %1; cvt.u32.u64 %0, t; }" : "=r"(a) : "l"(p));
    return a;
}
__device__ __forceinline__ void cp16(uint32_t saddr, const void* g) {
    asm volatile("cp.async.cg.shared.global [%0], [%1], 16;" :: "r"(saddr), "l"(g));
}
#define CP_COMMIT() asm volatile("cp.async.commit_group;" ::: "memory")
#define CP_WAIT(n)  asm volatile("cp.async.wait_group %0;" :: "n"(n) : "memory")

__device__ __forceinline__ void ldsm_x4(uint32_t* r, uint32_t addr) {
    asm volatile("ldmatrix.sync.aligned.m8n8.x4.shared.b16 {%0,%1,%2,%3}, [%4];"
                 : "=r"(r[0]), "=r"(r[1]), "=r"(r[2]), "=r"(r[3]) : "r"(addr));
}
__device__ __forceinline__ void ldsm_x4_t(uint32_t* r, uint32_t addr) {
    asm volatile("ldmatrix.sync.aligned.m8n8.x4.trans.shared.b16 {%0,%1,%2,%3}, [%4];"
                 : "=r"(r[0]), "=r"(r[1]), "=r"(r[2]), "=r"(r[3]) : "r"(addr));
}
__device__ __forceinline__ void mma_f16(float* c, const uint32_t* a, const uint32_t* b) {
    asm volatile(
        "mma.sync.aligned.m16n8k16.row.col.f32.f16.f16.f32 "
        "{%0,%1,%2,%3}, {%4,%5,%6,%7}, {%8,%9}, {%0,%1,%2,%3};"
        : "+f"(c[0]), "+f"(c[1]), "+f"(c[2]), "+f"(c[3])
        : "r"(a[0]), "r"(a[1]), "r"(a[2]), "r"(a[3]), "r"(b[0]), "r"(b[1]));
}
__device__ __forceinline__ uint32_t swz(uint32_t off) {  // SW128
    return off ^ ((off >> 3) & 0x70);
}
__device__ __forceinline__ uint32_t pkh(__half a, __half b) {
    uint16_t x = *(uint16_t*)&a, y = *(uint16_t*)&b;
    return ((uint32_t)y << 16) | x;
}

// ---------------------------------------------------------------------------
// prep kernels (R14: transposed weight layout — proven fastest GEMM path)
// ---------------------------------------------------------------------------
__global__ __launch_bounds__(256) void conv2h(
    const float* __restrict__ x, __half* __restrict__ o, int n4)
{
    int i = blockIdx.x * 256 + threadIdx.x;
    if (i >= n4) return;
    float4 v = *((const float4*)x + i);
    ((uint32_t*)o)[i * 2]     = pkh(__float2half(v.x), __float2half(v.y));
    ((uint32_t*)o)[i * 2 + 1] = pkh(__float2half(v.z), __float2half(v.w));
}

// transpose + fp16 round: in [K,N] fp32 row-major -> out [N,K] fp16
__global__ __launch_bounds__(256) void tsplit_h(
    const float* __restrict__ in, __half* __restrict__ oh, int K, int N)
{
    __shared__ float t[32][33];
    int n0 = blockIdx.x * 32, k0 = blockIdx.y * 32;
    int tx = threadIdx.x & 31, ty = threadIdx.x >> 5;
    #pragma unroll
    for (int r = ty; r < 32; r += 8)
        t[r][tx] = in[(size_t)(k0 + r) * N + n0 + tx];
    __syncthreads();
    #pragma unroll
    for (int r = ty; r < 32; r += 8)
        oh[(size_t)(n0 + r) * K + k0 + tx] = __float2half(t[tx][r]);
}

// ---------------------------------------------------------------------------
// fp16 GEMM (EXACT R12/R14 configuration — proven): C = A @ B^T, 1 MMA/tile.
// CTA 128x128, 8 warps, warp tile 64x32, 2-stage cp.async, 2 CTAs/SM.
// ---------------------------------------------------------------------------
#define GSTG1 32768

__global__ __launch_bounds__(256, 2) void gemm_fp16(
    const __half* __restrict__ A, const __half* __restrict__ B,
    float* __restrict__ C, int M, int N, int K)
{
    extern __shared__ __align__(128) char smem[];
    const uint32_t sbase = smem_u32(smem);
    const int tid = threadIdx.x;
    const int wid = tid >> 5, lane = tid & 31;
    const int bm = blockIdx.y * 128, bn = blockIdx.x * 128;

    const __half* srcs[2] = { A + (size_t)bm * K, B + (size_t)bn * K };

    const int nchunks = K / KC_;

    auto load_stage = [&](int c, int buf) {
        const int k0 = c * KC_;
        #pragma unroll
        for (int t = 0; t < 2; t++) {
            const __half* g = srcs[t] + k0;
            uint32_t db = sbase + (uint32_t)buf * GSTG1 + (uint32_t)t * 16384;
            #pragma unroll
            for (int it = 0; it < 4; it++) {
                int i = tid + it * 256;
                int row = i >> 3, c8 = i & 7;
                cp16(db + swz((uint32_t)(row * 128 + c8 * 16)),
                     g + (size_t)row * K + c8 * 8);
            }
        }
    };

    load_stage(0, 0); CP_COMMIT();
    if (nchunks > 1) load_stage(1, 1);
    CP_COMMIT();

    const int wm = wid >> 2, wn = wid & 3;
    const int m0 = wm * 64, n0 = wn * 32;

    float acc[4][4][4];
    #pragma unroll
    for (int i = 0; i < 4; i++)
        #pragma unroll
        for (int j = 0; j < 4; j++)
            #pragma unroll
            for (int k = 0; k < 4; k++) acc[i][j][k] = 0.f;

    const int aRow = (lane & 15);
    const int aKb  = (lane >> 4) * 16;
    const int bRow = (lane & 7) + ((lane >> 4) & 1) * 8;
    const int bKb  = ((lane >> 3) & 1) * 16;

    for (int c = 0; c < nchunks; c++) {
        CP_WAIT(1);
        __syncthreads();
        const int buf = c & 1;
        const uint32_t sA = sbase + (uint32_t)buf * GSTG1;
        const uint32_t sB = sA + 16384;

        #pragma unroll
        for (int ks = 0; ks < 4; ks++) {
            const uint32_t akb = (uint32_t)(ks * 32 + aKb);
            const uint32_t bkb = (uint32_t)(ks * 32 + bKb);
            uint32_t af[4][4], bf[2][4];
            #pragma unroll
            for (int mt = 0; mt < 4; mt++) {
                uint32_t off = swz((uint32_t)((m0 + mt * 16 + aRow) * 128) + akb);
                ldsm_x4(af[mt], sA + off);
            }
            #pragma unroll
            for (int p = 0; p < 2; p++) {
                uint32_t off = swz((uint32_t)((n0 + p * 16 + bRow) * 128) + bkb);
                ldsm_x4(bf[p], sB + off);
            }
            #pragma unroll
            for (int mt = 0; mt < 4; mt++)
                #pragma unroll
                for (int nt = 0; nt < 4; nt++)
                    mma_f16(acc[mt][nt], af[mt], &bf[nt >> 1][(nt & 1) * 2]);
        }
        __syncthreads();
        if (c + 2 < nchunks) load_stage(c + 2, buf);
        CP_COMMIT();
    }

    const int er = lane >> 2, ec = (lane & 3) * 2;
    #pragma unroll
    for (int mt = 0; mt < 4; mt++)
        #pragma unroll
        for (int nt = 0; nt < 4; nt++) {
            int row = bm + m0 + mt * 16 + er;
            int col = bn + n0 + nt * 8 + ec;
            *(float2*)(C + (size_t)row * N + col) =
                make_float2(acc[mt][nt][0], acc[mt][nt][1]);
            *(float2*)(C + (size_t)(row + 8) * N + col) =
                make_float2(acc[mt][nt][2], acc[mt][nt][3]);
        }
}

// ---------------------------------------------------------------------------
// QKV GEMM with fused RoPE epilogue (EXACT R14 version — proven).
// ---------------------------------------------------------------------------
__global__ __launch_bounds__(256, 2) void gemm_qkv(
    const __half* __restrict__ A, const __half* __restrict__ B,
    const float* __restrict__ rope_cos, const float* __restrict__ rope_sin,
    __half* __restrict__ q_out, __half* __restrict__ k_out,
    __half* __restrict__ v_out, int M, int N, int K)
{
    extern __shared__ __align__(128) char smem[];
    const uint32_t sbase = smem_u32(smem);
    const int tid = threadIdx.x;
    const int wid = tid >> 5, lane = tid & 31;
    const int bm = blockIdx.y * 128, bn = blockIdx.x * 128;

    const __half* srcs[2] = { A + (size_t)bm * K, B + (size_t)bn * K };

    const int nchunks = K / KC_;

    auto load_stage = [&](int c, int buf) {
        const int k0 = c * KC_;
        #pragma unroll
        for (int t = 0; t < 2; t++) {
            const __half* g = srcs[t] + k0;
            uint32_t db = sbase + (uint32_t)buf * GSTG1 + (uint32_t)t * 16384;
            #pragma unroll
            for (int it = 0; it < 4; it++) {
                int i = tid + it * 256;
                int row = i >> 3, c8 = i & 7;
                cp16(db + swz((uint32_t)(row * 128 + c8 * 16)),
                     g + (size_t)row * K + c8 * 8);
            }
        }
    };

    load_stage(0, 0); CP_COMMIT();
    if (nchunks > 1) load_stage(1, 1);
    CP_COMMIT();

    const int wm = wid >> 2, wn = wid & 3;
    const int m0 = wm * 64, n0 = wn * 32;

    float acc[4][4][4];
    #pragma unroll
    for (int i = 0; i < 4; i++)
        #pragma unroll
        for (int j = 0; j < 4; j++)
            #pragma unroll
            for (int k = 0; k < 4; k++) acc[i][j][k] = 0.f;

    const int aRow = (lane & 15);
    const int aKb  = (lane >> 4) * 16;
    const int bRow = (lane & 7) + ((lane >> 4) & 1) * 8;
    const int bKb  = ((lane >> 3) & 1) * 16;

    for (int c = 0; c < nchunks; c++) {
        CP_WAIT(1);
        __syncthreads();
        const int buf = c & 1;
        const uint32_t sA = sbase + (uint32_t)buf * GSTG1;
        const uint32_t sB = sA + 16384;

        #pragma unroll
        for (int ks = 0; ks < 4; ks++) {
            const uint32_t akb = (uint32_t)(ks * 32 + aKb);
            const uint32_t bkb = (uint32_t)(ks * 32 + bKb);
            uint32_t af[4][4], bf[2][4];
            #pragma unroll
            for (int mt = 0; mt < 4; mt++) {
                uint32_t off = swz((uint32_t)((m0 + mt * 16 + aRow) * 128) + akb);
                ldsm_x4(af[mt], sA + off);
            }
            #pragma unroll
            for (int p = 0; p < 2; p++) {
                uint32_t off = swz((uint32_t)((n0 + p * 16 + bRow) * 128) + bkb);
                ldsm_x4(bf[p], sB + off);
            }
            #pragma unroll
            for (int mt = 0; mt < 4; mt++)
                #pragma unroll
                for (int nt = 0; nt < 4; nt++)
                    mma_f16(acc[mt][nt], af[mt], &bf[nt >> 1][(nt & 1) * 2]);
        }
        __syncthreads();
        if (c + 2 < nchunks) load_stage(c + 2, buf);
        CP_COMMIT();
    }

    // ---- fused RoPE epilogue ----
    __syncthreads();
    float* smf = (float*)smem;               // fp32 tile [128][132]
    const int er = lane >> 2, ec = (lane & 3) * 2;
    #pragma unroll
    for (int mt = 0; mt < 4; mt++)
        #pragma unroll
        for (int nt = 0; nt < 4; nt++) {
            int r = m0 + mt * 16 + er;
            int cc = n0 + nt * 8 + ec;
            smf[r * 132 + cc]           = acc[mt][nt][0];
            smf[r * 132 + cc + 1]       = acc[mt][nt][1];
            smf[(r + 8) * 132 + cc]     = acc[mt][nt][2];
            smf[(r + 8) * 132 + cc + 1] = acc[mt][nt][3];
        }
    __syncthreads();

    const int chunk = (int)blockIdx.x % 6;   // 0-3: q heads, 4: k, 5: v
    const int grp   = (int)blockIdx.x / 6;   // kv group
    const float qscale = 0.08838834764831845f * 1.4426950408889634f;

    #pragma unroll 4
    for (int it = 0; it < 32; it++) {
        int p = tid + it * 256;
        int r = p >> 6, dd = (p & 63) * 2;
        int tok = bm + r, b = tok >> 11, s = tok & 2047;
        float v0 = smf[r * 132 + dd], v1 = smf[r * 132 + dd + 1];
        if (chunk < 5) {
            float o0, o1;
            if (dd < 64) { o0 = -smf[r * 132 + dd + 64]; o1 = -smf[r * 132 + dd + 65]; }
            else         { o0 =  smf[r * 132 + dd - 64]; o1 =  smf[r * 132 + dd - 63]; }
            float2 cs = *(const float2*)(rope_cos + (size_t)s * HD_ + dd);
            float2 sn = *(const float2*)(rope_sin + (size_t)s * HD_ + dd);
            v0 = v0 * cs.x + o0 * sn.x;
            v1 = v1 * cs.y + o1 * sn.y;
            if (chunk < 4) { v0 *= qscale; v1 *= qscale; }
        }
        uint32_t pv = pkh(__float2half(v0), __float2half(v1));
        if (chunk < 4) {
            int hh = grp * 4 + chunk;
            *(uint32_t*)(q_out + (((size_t)b * NH_ + hh) * S_ + s) * HD_ + dd) = pv;
        } else if (chunk == 4) {
            *(uint32_t*)(k_out + (((size_t)b * NKV_ + grp) * S_ + s) * HD_ + dd) = pv;
        } else {
            *(uint32_t*)(v_out + (((size_t)b * NKV_ + grp) * S_ + s) * HD_ + dd) = pv;
        }
    }
}

// ---------------------------------------------------------------------------
// Tensor-core causal flash attention, single fp16, GQA.
// R16 change: K/V stages of 128 keys (two 64-key sub-tiles per buffer):
// halves CP_WAIT/barrier/prefetch count. Diagonal stage: warps 0-3 skip
// the fully-masked second sub-tile (intra-warp reductions make this safe).
// smem: Q 32KB + 2 stages x (K 32KB + V 32KB) = 160KB. 1 CTA/SM.
// ---------------------------------------------------------------------------
__global__ __launch_bounds__(256, 1) void flash_mma(
    const __half* __restrict__ Q, const __half* __restrict__ Kh,
    const __half* __restrict__ Vh, __half* __restrict__ O_out)
{
    extern __shared__ __align__(128) char smem[];
    const uint32_t sb = smem_u32(smem);
    const int tid = threadIdx.x, lane = tid & 31, w = tid >> 5;
    const int qt = (int)(gridDim.x - 1) - (int)blockIdx.x;   // heavy tiles first
    const int h = blockIdx.y, b = blockIdx.z;
    const int kvh = h >> 2;

    const __half* gQ = Q + (((size_t)b * NH_ + h) * S_ + (size_t)qt * 128) * HD_;
    const size_t kvbase = ((size_t)b * NKV_ + kvh) * S_ * HD_;
    const __half* gKh = Kh + kvbase;
    const __half* gVh = Vh + kvbase;

    // ---- load Q tile: [hd_chunk(2)][row(128)][64 fp16] = 32KB ----
    #pragma unroll
    for (int it = 0; it < 8; it++) {
        int i = tid + it * 256;
        int row = i >> 4, c8 = i & 15;
        uint32_t so = (uint32_t)(c8 >> 3) * 16384 +
                      swz((uint32_t)(row * 128 + (c8 & 7) * 16));
        cp16(sb + so, gQ + (size_t)row * HD_ + c8 * 8);
    }
    CP_COMMIT();

    // K/V stage: 128 keys. K at +0 (32KB, [hd_chunk(2)][key(128)][64]), V at +32768.
    auto load_stage = [&](int st, int buf) {
        uint32_t o = 32768 + (uint32_t)buf * 65536;
        const size_t go = (size_t)st * 128 * HD_;
        #pragma unroll
        for (int it = 0; it < 8; it++) {
            int i = tid + it * 256;          // 2048 chunks per tensor
            int row = i >> 4, c8 = i & 15;
            uint32_t so = (uint32_t)(c8 >> 3) * 16384 +
                          swz((uint32_t)(row * 128 + (c8 & 7) * 16));
            size_t gof = go + (size_t)row * HD_ + c8 * 8;
            cp16(sb + o + so,         gKh + gof);
            cp16(sb + o + 32768 + so, gVh + gof);
        }
    };

    load_stage(0, 0);
    CP_COMMIT();

    const int nst = qt + 1;                  // 128-key stages

    float O[16][4];
    #pragma unroll
    for (int i = 0; i < 16; i++)
        #pragma unroll
        for (int j = 0; j < 4; j++) O[i][j] = 0.f;
    float mA = -1e30f, mB = -1e30f, lA = 0.f, lB = 0.f;

    const int aRow = lane & 15;
    const int aK16 = (lane >> 4) * 16;
    const int bRow = (lane & 7) + ((lane >> 4) & 1) * 8;
    const int bK16 = ((lane >> 3) & 1) * 16;

    for (int st = 0; st < nst; st++) {
        const int buf = st & 1;
        if (st + 1 < nst) { load_stage(st + 1, buf ^ 1); CP_COMMIT(); CP_WAIT(1); }
        else              { CP_WAIT(0); }
        __syncthreads();

        const uint32_t sK = sb + 32768 + (uint32_t)buf * 65536;
        const uint32_t sV = sK + 32768;

        #pragma unroll
        for (int hh = 0; hh < 2; hh++) {
            // diagonal stage: second sub-tile fully masked for warps 0-3
            if (st == qt && hh == 1 && w < 4) continue;
            const int krow0 = hh * 64;

            // ---- S = Q K^T (1 MMA), log2 domain ----
            float S[8][4];
            #pragma unroll
            for (int i = 0; i < 8; i++)
                #pragma unroll
                for (int j = 0; j < 4; j++) S[i][j] = 0.f;

            #pragma unroll
            for (int ks = 0; ks < 8; ks++) {
                uint32_t qo = (uint32_t)(ks >> 2) * 16384 +
                              swz((uint32_t)((w * 16 + aRow) * 128 + (ks & 3) * 32 + aK16));
                uint32_t qf[4];
                ldsm_x4(qf, sb + qo);
                #pragma unroll
                for (int g = 0; g < 4; g++) {
                    uint32_t ko = (uint32_t)(ks >> 2) * 16384 +
                                  swz((uint32_t)((krow0 + g * 16 + bRow) * 128 +
                                                 (ks & 3) * 32 + bK16));
                    uint32_t khf[4];
                    ldsm_x4(khf, sK + ko);
                    #pragma unroll
                    for (int p = 0; p < 2; p++)
                        mma_f16(S[g * 2 + p], qf, &khf[p * 2]);
                }
            }

            // ---- causal mask (diagonal stage only) ----
            if (st == qt) {
                const int rA = qt * 128 + w * 16 + (lane >> 2);
                #pragma unroll
                for (int nt = 0; nt < 8; nt++) {
                    int key0 = st * 128 + krow0 + nt * 8 + (lane & 3) * 2;
                    if (key0     > rA)     S[nt][0] = -1e30f;
                    if (key0 + 1 > rA)     S[nt][1] = -1e30f;
                    if (key0     > rA + 8) S[nt][2] = -1e30f;
                    if (key0 + 1 > rA + 8) S[nt][3] = -1e30f;
                }
            }

            // ---- online softmax (base-2) ----
            float mxA = -1e30f, mxB = -1e30f;
            #pragma unroll
            for (int nt = 0; nt < 8; nt++) {
                mxA = fmaxf(mxA, fmaxf(S[nt][0], S[nt][1]));
                mxB = fmaxf(mxB, fmaxf(S[nt][2], S[nt][3]));
            }
            #pragma unroll
            for (int off = 1; off < 4; off <<= 1) {
                mxA = fmaxf(mxA, __shfl_xor_sync(0xffffffffu, mxA, off));
                mxB = fmaxf(mxB, __shfl_xor_sync(0xffffffffu, mxB, off));
            }
            float mAn = fmaxf(mA, mxA), mBn = fmaxf(mB, mxB);
            float aAl = exp2f(mA - mAn), aBl = exp2f(mB - mBn);
            mA = mAn; mB = mBn;

            float sumA = 0.f, sumB = 0.f;
            #pragma unroll
            for (int nt = 0; nt < 8; nt++) {
                S[nt][0] = exp2f(S[nt][0] - mA);
                S[nt][1] = exp2f(S[nt][1] - mA);
                S[nt][2] = exp2f(S[nt][2] - mB);
                S[nt][3] = exp2f(S[nt][3] - mB);
                sumA += S[nt][0] + S[nt][1];
                sumB += S[nt][2] + S[nt][3];
            }
            #pragma unroll
            for (int off = 1; off < 4; off <<= 1) {
                sumA += __shfl_xor_sync(0xffffffffu, sumA, off);
                sumB += __shfl_xor_sync(0xffffffffu, sumB, off);
            }
            lA = lA * aAl + sumA;
            lB = lB * aBl + sumB;
            #pragma unroll
            for (int nt = 0; nt < 16; nt++) {
                O[nt][0] *= aAl; O[nt][1] *= aAl;
                O[nt][2] *= aBl; O[nt][3] *= aBl;
            }

            // ---- O += P V (1 MMA; V via ldmatrix.trans) ----
            #pragma unroll
            for (int kk = 0; kk < 4; kk++) {
                uint32_t ah[4];
                ah[0] = pkh(__float2half(S[2 * kk][0]),     __float2half(S[2 * kk][1]));
                ah[1] = pkh(__float2half(S[2 * kk][2]),     __float2half(S[2 * kk][3]));
                ah[2] = pkh(__float2half(S[2 * kk + 1][0]), __float2half(S[2 * kk + 1][1]));
                ah[3] = pkh(__float2half(S[2 * kk + 1][2]), __float2half(S[2 * kk + 1][3]));
                #pragma unroll
                for (int g = 0; g < 8; g++) {
                    uint32_t vo = (uint32_t)(g >> 2) * 16384 +
                                  swz((uint32_t)((krow0 + kk * 16 + (lane & 15)) * 128 +
                                                 (g & 3) * 32 + (lane >> 4) * 16));
                    uint32_t vhf[4];
                    ldsm_x4_t(vhf, sV + vo);
                    #pragma unroll
                    for (int p = 0; p < 2; p++)
                        mma_f16(O[g * 2 + p], ah, &vhf[p * 2]);
                }
            }
        }
        __syncthreads();
    }

    // ---- epilogue: O/l -> single fp16 at [B, S, NH*HD] ----
    const float iA = 1.f / lA, iB = 1.f / lB;
    const int sA = qt * 128 + w * 16 + (lane >> 2);
    const size_t baseA = ((size_t)b * S_ + sA) * H_ + (size_t)h * HD_;
    const size_t baseB = baseA + (size_t)8 * H_;
    #pragma unroll
    for (int nt = 0; nt < 16; nt++) {
        int col = nt * 8 + (lane & 3) * 2;
        *(uint32_t*)(O_out + baseA + col) =
            pkh(__float2half(O[nt][0] * iA), __float2half(O[nt][1] * iA));
        *(uint32_t*)(O_out + baseB + col) =
            pkh(__float2half(O[nt][2] * iB), __float2half(O[nt][3] * iB));
    }
}

// ---------------------------------------------------------------------------
// Launch
// ---------------------------------------------------------------------------
extern "C" void kernel_launch(void* const* d_in, const int* in_sizes, int n_in,
                              void* d_out, int out_size)
{
    (void)in_sizes; (void)n_in; (void)out_size;
    const float* hidden   = (const float*)d_in[0];
    // d_in[1] = attention_mask: structurally causal, unused (exp(-1e9) == 0 in fp32)
    const float* rope_cos = (const float*)d_in[2];
    const float* rope_sin = (const float*)d_in[3];
    const float* w_attn   = (const float*)d_in[4];
    const float* w_proj   = (const float*)d_in[5];
    float* out = (float*)d_out;

    __half *p_x, *p_wa, *p_wp, *p_q, *p_k, *p_v;
    cudaGetSymbolAddress((void**)&p_x, g_x);
    cudaGetSymbolAddress((void**)&p_wa, g_wa);
    cudaGetSymbolAddress((void**)&p_wp, g_wp);
    cudaGetSymbolAddress((void**)&p_q, g_q);
    cudaGetSymbolAddress((void**)&p_k, g_k);
    cudaGetSymbolAddress((void**)&p_v, g_v);

    const int gemm_smem = 2 * GSTG1;            // 64 KB
    cudaFuncSetAttribute(gemm_fp16, cudaFuncAttributeMaxDynamicSharedMemorySize, gemm_smem);
    const int qkv_smem = 128 * 132 * 4;         // 67.6 KB
    cudaFuncSetAttribute(gemm_qkv, cudaFuncAttributeMaxDynamicSharedMemorySize, qkv_smem);
    const int flash_smem = 32768 + 2 * 65536;   // 160 KB
    cudaFuncSetAttribute(flash_mma, cudaFuncAttributeMaxDynamicSharedMemorySize, flash_smem);

    const int MTOK = B_ * S_;

    // 0) prep: transpose+round weights to fp16, convert hidden to fp16
    tsplit_h<<<dim3(F_ / 32, H_ / 32), 256>>>(w_attn, p_wa, H_, F_);
    tsplit_h<<<dim3(H_ / 32, H_ / 32), 256>>>(w_proj, p_wp, H_, H_);
    conv2h<<<(MTOK * H_ / 4 + 255) / 256, 256>>>(hidden, p_x, MTOK * H_ / 4);

    // 1) QKV projection + fused RoPE -> q/k/v fp16 heads directly
    gemm_qkv<<<dim3(F_ / 128, MTOK / 128), 256, qkv_smem>>>(
        p_x, p_wa, rope_cos, rope_sin, p_q, p_k, p_v, MTOK, F_, H_);

    // 2) Tensor-core causal flash attention (fp16) -> x (fp16)
    flash_mma<<<dim3(S_ / 128, NH_, B_), 256, flash_smem>>>(p_q, p_k, p_v, p_x);

    // 3) output projection (fp16 in, fp32 out): [8192,2048] @ [2048,2048]
    gemm_fp16<<<dim3(H_ / 128, MTOK / 128), 256, gemm_smem>>>(
        p_x, p_wp, out, MTOK, H_, H_);
}